// round 4
// baseline (speedup 1.0000x reference)
#include <cuda_runtime.h>
#include <cuda_bf16.h>
#include <cstdint>
#include <cstddef>
#include <math.h>

#define NB   32      // batch
#define T1   2000    // layer-1 time steps
#define T2   1000    // layer-2 time steps (after pool s=2)
#define D1   80      // input feature dim
#define HH   256     // hidden per direction
#define G4H  1024    // 4*H gate rows
#define HDC  512     // 2*H (bidirectional concat)
#define OUTC 512     // final output channels

typedef unsigned long long ull;

// ---------------- f32x2 packed-FMA helpers (Blackwell FFMA2) -----------------
__device__ __forceinline__ void fma2(ull& d, ull a, ull b) {
    asm("fma.rn.f32x2 %0, %1, %2, %3;" : "=l"(d) : "l"(a), "l"(b), "l"(d));
}
__device__ __forceinline__ ull dup2(float x) {
    ull r; asm("mov.b64 %0, {%1, %1};" : "=l"(r) : "f"(x)); return r;
}
__device__ __forceinline__ float2 unp2(ull v) {
    float2 r; asm("mov.b64 {%0, %1}, %2;" : "=f"(r.x), "=f"(r.y) : "l"(v)); return r;
}
__device__ __forceinline__ ulonglong2 ldcg2(const ulonglong2* p) {
    ulonglong2 v;
    asm volatile("ld.global.cg.v2.u64 {%0,%1}, [%2];" : "=l"(v.x), "=l"(v.y) : "l"(p));
    return v;
}

// ---------------- device scratch (static: allocation is forbidden) ----------
__device__ float g_xg1f[(size_t)T1 * G4H * NB];   // [t][gate_row][b]
__device__ float g_xg1b[(size_t)T1 * G4H * NB];
__device__ float g_xg2f[(size_t)T2 * G4H * NB];
__device__ float g_xg2b[(size_t)T2 * G4H * NB];
__device__ float g_out1[(size_t)NB * T1 * HDC];   // [b][t][ch]
__device__ float g_pool1[(size_t)NB * T2 * HDC];
__device__ float g_out2[(size_t)NB * T2 * HDC];
__device__ float g_hbuf[2 * 2 * HH * NB];         // [dir][parity][k][b]
__device__ unsigned g_barCnt;
__device__ volatile unsigned g_barGen;

// ---------------- small helpers ---------------------------------------------
__global__ void k_zero(float* __restrict__ p, size_t n) {
    size_t i = (size_t)blockIdx.x * blockDim.x + threadIdx.x;
    size_t st = (size_t)gridDim.x * blockDim.x;
    for (; i < n; i += st) p[i] = 0.f;
}

__global__ void k_init_rec() {
    for (int j = threadIdx.x; j < 2 * 2 * HH * NB; j += blockDim.x) g_hbuf[j] = 0.f;
    if (threadIdx.x == 0) { g_barCnt = 0u; g_barGen = 0u; }
}

__global__ void k_pool(const float* __restrict__ in, float* __restrict__ out) {
    size_t n = (size_t)NB * T2 * HDC;
    size_t i = (size_t)blockIdx.x * blockDim.x + threadIdx.x;
    size_t st = (size_t)gridDim.x * blockDim.x;
    for (; i < n; i += st) {
        int c  = (int)(i % HDC);
        size_t r = i / HDC;
        int tp = (int)(r % T2);
        int b  = (int)(r / T2);
        const float* p = in + ((size_t)b * T1 + 2 * (size_t)tp) * HDC + c;
        out[i] = fmaxf(p[0], p[HDC]);
    }
}

__global__ void k_lens(const int* __restrict__ xlen, float* __restrict__ out) {
    int i = threadIdx.x;
    if (i < NB) out[i] = (float)(xlen[i] >> 1);
}

// ---------------- projection / linear GEMM (f32x2 packed) --------------------
// C[row][n] = bias[row] + sum_k W[row][k] * X[n][k], n = b*TT + t.
// Block: 64 rows x 64 cols, 128 threads, thread tile 4x8, K chunk 16.
// Requires: K % 16 == 0, M % 64 == 0, N % 64 == 0 (true for all call sites).
template <int TT>
__global__ void __launch_bounds__(128) k_proj(
    const float* __restrict__ X, const float* __restrict__ W,
    const float* __restrict__ bias, float* __restrict__ out,
    int K, long long ot, long long orr, long long ob)
{
    __shared__ __align__(16) ull   a2[16][66];    // [k][row] weights, pre-duplicated
    __shared__ __align__(16) float xs[16][68];    // [k][col]

    const int row0 = blockIdx.x * 64;
    const int n0   = blockIdx.y * 64;
    const int tid  = threadIdx.x;
    const int rgp  = tid >> 3;   // 0..15 -> rows rgp*4 .. +3
    const int cgp  = tid & 7;    // 0..7  -> cols cgp*8 .. +7

    ull acc2[4][4] = {};         // [row][col-pair]

    const int r  = tid >> 1;             // staging row/col index (0..63)
    const int kq = (tid & 1) * 8;        // staging k offset (0 or 8)

    for (int k0 = 0; k0 < K; k0 += 16) {
        // stage W chunk 64x16, duplicated into f32x2 lanes
        {
            const float* wp = W + (size_t)(row0 + r) * K + k0 + kq;
            float4 v0 = *(const float4*)wp;
            float4 v1 = *(const float4*)(wp + 4);
            a2[kq + 0][r] = dup2(v0.x); a2[kq + 1][r] = dup2(v0.y);
            a2[kq + 2][r] = dup2(v0.z); a2[kq + 3][r] = dup2(v0.w);
            a2[kq + 4][r] = dup2(v1.x); a2[kq + 5][r] = dup2(v1.y);
            a2[kq + 6][r] = dup2(v1.z); a2[kq + 7][r] = dup2(v1.w);
        }
        // stage X chunk 64x16 (transposed)
        {
            const float* xp = X + (size_t)(n0 + r) * K + k0 + kq;
            float4 u0 = *(const float4*)xp;
            float4 u1 = *(const float4*)(xp + 4);
            xs[kq + 0][r] = u0.x; xs[kq + 1][r] = u0.y;
            xs[kq + 2][r] = u0.z; xs[kq + 3][r] = u0.w;
            xs[kq + 4][r] = u1.x; xs[kq + 5][r] = u1.y;
            xs[kq + 6][r] = u1.z; xs[kq + 7][r] = u1.w;
        }
        __syncthreads();
#pragma unroll
        for (int kk = 0; kk < 16; kk++) {
            ulonglong2 a01 = *(const ulonglong2*)&a2[kk][rgp * 4];
            ulonglong2 a23 = *(const ulonglong2*)&a2[kk][rgp * 4 + 2];
            ulonglong2 b01 = *(const ulonglong2*)&xs[kk][cgp * 8];
            ulonglong2 b23 = *(const ulonglong2*)&xs[kk][cgp * 8 + 4];
            fma2(acc2[0][0], a01.x, b01.x); fma2(acc2[0][1], a01.x, b01.y);
            fma2(acc2[0][2], a01.x, b23.x); fma2(acc2[0][3], a01.x, b23.y);
            fma2(acc2[1][0], a01.y, b01.x); fma2(acc2[1][1], a01.y, b01.y);
            fma2(acc2[1][2], a01.y, b23.x); fma2(acc2[1][3], a01.y, b23.y);
            fma2(acc2[2][0], a23.x, b01.x); fma2(acc2[2][1], a23.x, b01.y);
            fma2(acc2[2][2], a23.x, b23.x); fma2(acc2[2][3], a23.x, b23.y);
            fma2(acc2[3][0], a23.y, b01.x); fma2(acc2[3][1], a23.y, b01.y);
            fma2(acc2[3][2], a23.y, b23.x); fma2(acc2[3][3], a23.y, b23.y);
        }
        __syncthreads();
    }

#pragma unroll
    for (int i = 0; i < 4; i++) {
        const int row = row0 + rgp * 4 + i;
        const float bv = bias[row];
#pragma unroll
        for (int p = 0; p < 4; p++) {
            float2 v = unp2(acc2[i][p]);
            int n = n0 + cgp * 8 + 2 * p;
            int b = n / TT, t = n - b * TT;
            out[(size_t)t * ot + (size_t)row * orr + (size_t)b * ob] = v.x + bv;
            n += 1; b = n / TT; t = n - b * TT;
            out[(size_t)t * ot + (size_t)row * orr + (size_t)b * ob] = v.y + bv;
        }
    }
}

// ---------------- persistent recurrent LSTM (f32x2) --------------------------
__device__ __forceinline__ float fsig(float x) {
    return 1.f / (1.f + __expf(-x));
}
__device__ __forceinline__ float ftanh(float x) {
    float e = __expf(2.f * x);
    return 1.f - 2.f / (e + 1.f);
}

__global__ void __launch_bounds__(128, 1) k_lstm(
    const float* __restrict__ xgF, const float* __restrict__ xgB,
    const float* __restrict__ WhhF, const float* __restrict__ WhhB,
    const int* __restrict__ xlen, int lenShift,
    float* __restrict__ out, int Tt)
{
    __shared__ __align__(16) ull   w2[HH * 16];      // [k][rr], rr = gate*4+j, duplicated
    __shared__ __align__(16) float part[4 * 16 * NB];

    const int dir = (int)(blockIdx.x >> 6);
    const int gb  = (int)(blockIdx.x & 63);
    const float* xg  = dir ? xgB : xgF;
    const float* Whh = dir ? WhhB : WhhF;
    float* hb = g_hbuf + dir * (2 * HH * NB);

    const int tid  = threadIdx.x;
    const int warp = tid >> 5, lane = tid & 31;
    const int bg = lane >> 2;     // batch group 0..7
    const int rg = lane & 3;      // gate group 0..3
    const int kbase = warp * 64;  // K section per warp

    // stage Whh slice transposed + duplicated: w2[k*16 + rr], row(rr) = gate*256 + gb*4 + j
    {
        const int rr = tid & 15, kp = tid >> 4;    // kp 0..7
        const int grow = (rr >> 2) * HH + gb * 4 + (rr & 3);
        const float* wp = Whh + (size_t)grow * HH + kp * 32;
#pragma unroll
        for (int j = 0; j < 32; j++) w2[(size_t)(kp * 32 + j) * 16 + rr] = dup2(wp[j]);
    }

    // pointwise role: thread owns (hj = warp, b = lane)
    const int b_pt = lane;
    const int hj   = warp;
    const int hk   = gb * 4 + hj;
    const int len_b = xlen[b_pt] >> lenShift;
    float c_st = 0.f, h_st = 0.f;

    __syncthreads();

    // gate-input prefetch for step 0
    float xg0, xg1, xg2, xg3;
    {
        int tx = dir ? (len_b - 1) : 0;
        if (tx < 0) tx = 0;
        const float* xp = xg + (size_t)tx * (G4H * NB) + (size_t)hk * NB + b_pt;
        xg0 = __ldg(xp);
        xg1 = __ldg(xp + 256 * NB);
        xg2 = __ldg(xp + 512 * NB);
        xg3 = __ldg(xp + 768 * NB);
    }

    for (int s = 0; s < Tt; s++) {
        const float* hrd = hb + (s & 1) * (HH * NB);
        float* hwr = hb + ((s & 1) ^ 1) * (HH * NB);

        // GEMM slice: rows (gate rg, j 0..3), batches bg*4..+3, K section [kbase,kbase+64)
        ull acc2[4][2] = {};
        const ulonglong2* hp  = (const ulonglong2*)hrd + (size_t)kbase * 8 + bg;
        const ulonglong2* wp2 = (const ulonglong2*)w2 + (size_t)kbase * 8 + rg * 2;
#pragma unroll 8
        for (int k = 0; k < 64; k++) {
            ulonglong2 hv   = ldcg2(hp + (size_t)k * 8);   // (b0,b1),(b2,b3) from L2
            ulonglong2 wv01 = wp2[(size_t)k * 8];
            ulonglong2 wv23 = wp2[(size_t)k * 8 + 1];
            fma2(acc2[0][0], wv01.x, hv.x); fma2(acc2[0][1], wv01.x, hv.y);
            fma2(acc2[1][0], wv01.y, hv.x); fma2(acc2[1][1], wv01.y, hv.y);
            fma2(acc2[2][0], wv23.x, hv.x); fma2(acc2[2][1], wv23.x, hv.y);
            fma2(acc2[3][0], wv23.y, hv.x); fma2(acc2[3][1], wv23.y, hv.y);
        }

        // cross-warp partials
#pragma unroll
        for (int i = 0; i < 4; i++) {
            float2 u0 = unp2(acc2[i][0]);
            float2 u1 = unp2(acc2[i][1]);
            *(float4*)(part + ((size_t)warp * 16 + rg * 4 + i) * NB + bg * 4) =
                make_float4(u0.x, u0.y, u1.x, u1.y);
        }
        __syncthreads();

        // reduce + pointwise update for (hj, b_pt)
        float g0 = xg0, g1 = xg1, g2 = xg2, g3 = xg3;
#pragma unroll
        for (int w = 0; w < 4; w++) {
            const float* pr = part + (size_t)w * 16 * NB;
            g0 += pr[(0  + hj) * NB + b_pt];
            g1 += pr[(4  + hj) * NB + b_pt];
            g2 += pr[(8  + hj) * NB + b_pt];
            g3 += pr[(12 + hj) * NB + b_pt];
        }
        float ig = fsig(g0);
        float fg = fsig(g1);
        float gg = ftanh(g2);
        float og = fsig(g3);
        float c_n = fg * c_st + ig * gg;
        float h_n = og * ftanh(c_n);
        if (s < len_b) {
            c_st = c_n; h_st = h_n;
            int t_o = dir ? (len_b - 1 - s) : s;
            out[((size_t)b_pt * Tt + t_o) * HDC + dir * HH + hk] = h_n;
        }
        hwr[hk * NB + b_pt] = h_st;
        __threadfence();

        // prefetch gate inputs for step s+1 (independent of barrier)
        {
            int sn = s + 1;
            int tx = dir ? (len_b - 1 - sn) : sn;
            if (tx < 0) tx = 0;
            if (tx >= Tt) tx = Tt - 1;
            const float* xp = xg + (size_t)tx * (G4H * NB) + (size_t)hk * NB + b_pt;
            xg0 = __ldg(xp);
            xg1 = __ldg(xp + 256 * NB);
            xg2 = __ldg(xp + 512 * NB);
            xg3 = __ldg(xp + 768 * NB);
        }

        // grid barrier (sense-reversal, 128 co-resident blocks)
        __syncthreads();
        if (tid == 0) {
            unsigned gen = g_barGen;
            if (atomicAdd(&g_barCnt, 1u) == 127u) {
                g_barCnt = 0u;
                __threadfence();
                g_barGen = gen + 1u;
            } else {
                while (g_barGen == gen) { }
            }
        }
        __syncthreads();
    }
}

// ---------------- host orchestration ----------------------------------------
extern "C" void kernel_launch(void* const* d_in, const int* in_sizes, int n_in,
                              void* d_out, int out_size) {
    const float* x     = (const float*)d_in[0];
    const int*   xlen  = (const int*)d_in[1];
    const float* Wih1f = (const float*)d_in[2];
    const float* Whh1f = (const float*)d_in[3];
    const float* b1f   = (const float*)d_in[4];
    const float* Wih1b = (const float*)d_in[5];
    const float* Whh1b = (const float*)d_in[6];
    const float* b1b   = (const float*)d_in[7];
    const float* Wih2f = (const float*)d_in[8];
    const float* Whh2f = (const float*)d_in[9];
    const float* b2f   = (const float*)d_in[10];
    const float* Wih2b = (const float*)d_in[11];
    const float* Whh2b = (const float*)d_in[12];
    const float* b2b   = (const float*)d_in[13];
    const float* Wlin  = (const float*)d_in[14];
    const float* blin  = (const float*)d_in[15];
    float* out = (float*)d_out;

    float *xg1f, *xg1b, *xg2f, *xg2b, *out1, *pool1, *out2;
    cudaGetSymbolAddress((void**)&xg1f,  g_xg1f);
    cudaGetSymbolAddress((void**)&xg1b,  g_xg1b);
    cudaGetSymbolAddress((void**)&xg2f,  g_xg2f);
    cudaGetSymbolAddress((void**)&xg2b,  g_xg2b);
    cudaGetSymbolAddress((void**)&out1,  g_out1);
    cudaGetSymbolAddress((void**)&pool1, g_pool1);
    cudaGetSymbolAddress((void**)&out2,  g_out2);

    const long long ot_xg = (long long)G4H * NB;   // xg layout [t][row][b]
    const long long or_xg = NB;
    const long long ob_xg = 1;

    // zero masked-output buffers (graph replays must rewrite every call)
    k_zero<<<4096, 256>>>(out1, (size_t)NB * T1 * HDC);
    k_zero<<<4096, 256>>>(out2, (size_t)NB * T2 * HDC);

    // layer-1 gate projections (M=1024, N=64000, K=80)
    k_proj<T1><<<dim3(G4H / 64, (NB * T1) / 64), 128>>>(x, Wih1f, b1f, xg1f, D1, ot_xg, or_xg, ob_xg);
    k_proj<T1><<<dim3(G4H / 64, (NB * T1) / 64), 128>>>(x, Wih1b, b1b, xg1b, D1, ot_xg, or_xg, ob_xg);

    // layer-1 recurrence
    k_init_rec<<<1, 256>>>();
    k_lstm<<<128, 128>>>(xg1f, xg1b, Whh1f, Whh1b, xlen, 0, out1, T1);

    // max-pool stride 2
    k_pool<<<2048, 256>>>(out1, pool1);

    // layer-2 gate projections (M=1024, N=32000, K=512)
    k_proj<T2><<<dim3(G4H / 64, (NB * T2) / 64), 128>>>(pool1, Wih2f, b2f, xg2f, HDC, ot_xg, or_xg, ob_xg);
    k_proj<T2><<<dim3(G4H / 64, (NB * T2) / 64), 128>>>(pool1, Wih2b, b2b, xg2b, HDC, ot_xg, or_xg, ob_xg);

    // layer-2 recurrence (lengths = x_len >> 1)
    k_init_rec<<<1, 256>>>();
    k_lstm<<<128, 128>>>(xg2f, xg2b, Whh2f, Whh2b, xlen, 1, out2, T2);

    // final linear: out[b][t][o], M=512, N=32000, K=512
    k_proj<T2><<<dim3(OUTC / 64, (NB * T2) / 64), 128>>>(out2, Wlin, blin, out, HDC,
                                                         (long long)OUTC, 1LL, (long long)T2 * OUTC);

    // lens = x_len // 2 appended as float (second tuple element)
    if (out_size > NB * T2 * OUTC) {
        k_lens<<<1, 32>>>(xlen, out + (size_t)NB * T2 * OUTC);
    }
}